// round 1
// baseline (speedup 1.0000x reference)
#include <cuda_runtime.h>
#include <cuda_bf16.h>
#include <mma.h>
#include <cstdint>

using namespace nvcuda;

// Problem constants
#define BB   8
#define DD   512
#define KK   32
#define NN   16384      // 128*128
#define TN   64         // n per subtile
#define CHUNK 512       // n per CTA
#define NSUB (CHUNK/TN) // 8

// SMEM pitches (floats). All multiples of 4 (tf32 wmma ld requirement).
#define XS_LD 68
#define CT_LD 36
#define AS_LD 36
#define ES_LD 516

// SMEM float counts
#define XS_F (DD*XS_LD)     // 34816
#define CT_F (DD*CT_LD)     // 18432
#define AS_F (TN*AS_LD)     // 2304
#define X2_F (4*TN)         // 256
#define SMEM_FLOATS (XS_F + CT_F + AS_F + X2_F + 32 /*S*/ + 32 /*c2*/ + 32 /*scale*/)
#define SMEM_BYTES (SMEM_FLOATS * 4)

__device__ __forceinline__ void cp_async16(void* smem_dst, const void* gmem_src) {
    uint32_t s = (uint32_t)__cvta_generic_to_shared(smem_dst);
    asm volatile("cp.async.cg.shared.global [%0], [%1], 16;\n" :: "r"(s), "l"(gmem_src));
}
__device__ __forceinline__ void cp_async_commit_wait() {
    asm volatile("cp.async.commit_group;\n" ::: "memory");
    asm volatile("cp.async.wait_group 0;\n" ::: "memory");
}

__global__ __launch_bounds__(256, 1)
void encoding_kernel(const float* __restrict__ X,
                     const float* __restrict__ CW,
                     const float* __restrict__ scale,
                     float* __restrict__ out)
{
    extern __shared__ float sm[];
    float* Xs  = sm;                 // [512][68]
    float* Ct  = Xs + XS_F;          // [512][36] codewords transposed: Ct[d][k]
    float* As  = Ct + CT_F;          // [64][36]  xc then A (softmax), in place
    float* x2p = As + AS_F;          // [4][64]
    float* Ssm = x2p + X2_F;         // [32] sum_n A[n][k] (per CTA)
    float* c2s = Ssm + 32;           // [32]
    float* scs = c2s + 32;           // [32]

    const int t = threadIdx.x;
    const int w = t >> 5;
    const int b = blockIdx.y;
    const int nbase = blockIdx.x * CHUNK;

    // ---- one-time staging: codewords transposed, scale, S=0 ----
    for (int i = t; i < KK * DD; i += 256) {
        int k = i >> 9, d = i & 511;
        Ct[d * CT_LD + k] = CW[i];           // coalesced read, scattered SMEM write (once)
    }
    if (t < 32) { Ssm[t] = 0.f; scs[t] = scale[t]; }
    __syncthreads();
    if (t < 32) {                            // c2[k] = ||c_k||^2 from SMEM (conflict-free)
        float s = 0.f;
        #pragma unroll 8
        for (int d = 0; d < DD; ++d) { float v = Ct[d * CT_LD + t]; s += v * v; }
        c2s[t] = s;
    }

    // ---- persistent GEMM2 accumulators: warp w owns d in [w*64, w*64+64) ----
    wmma::fragment<wmma::accumulator, 16, 16, 8, float> eacc[2][4];
    #pragma unroll
    for (int kc = 0; kc < 2; ++kc)
        #pragma unroll
        for (int dt = 0; dt < 4; ++dt)
            wmma::fill_fragment(eacc[kc][dt], 0.f);

    const float* Xb = X + (size_t)b * DD * NN;

    for (int s = 0; s < NSUB; ++s) {
        const int n0 = nbase + s * TN;

        // ---- stage X[d, n0:n0+64] -> Xs via cp.async (16B each) ----
        {
            const int j  = t & 15;   // n-quad within row
            const int dr = t >> 4;   // 16 d-rows per pass
            const float* src = Xb + n0 + j * 4;
            #pragma unroll
            for (int r = 0; r < 32; ++r) {
                int d = r * 16 + dr;
                cp_async16(&Xs[d * XS_LD + j * 4], src + (size_t)d * NN);
            }
            cp_async_commit_wait();
        }
        __syncthreads();

        // ---- x2 partials: thread (n = t&63, part = t>>6) sums 128 d each ----
        {
            const int n = t & 63, part = t >> 6;
            float acc = 0.f;
            #pragma unroll 8
            for (int j = 0; j < 128; ++j) {
                float v = Xs[(part * 128 + j) * XS_LD + n];
                acc += v * v;
            }
            x2p[part * TN + n] = acc;
        }

        // ---- GEMM1: P[n][k] = sum_d Xs[d][n] * Ct[d][k]  (tf32 wmma) ----
        {
            const int nc = w >> 1, kc = w & 1;   // 4 n-chunks x 2 k-chunks = 8 warp tiles
            wmma::fragment<wmma::accumulator, 16, 16, 8, float> p;
            wmma::fill_fragment(p, 0.f);
            #pragma unroll 4
            for (int ds = 0; ds < 64; ++ds) {
                wmma::fragment<wmma::matrix_a, 16, 16, 8, wmma::precision::tf32, wmma::col_major> a;
                wmma::fragment<wmma::matrix_b, 16, 16, 8, wmma::precision::tf32, wmma::row_major> bf;
                wmma::load_matrix_sync(a,  Xs + ds * 8 * XS_LD + nc * 16, XS_LD);
                wmma::load_matrix_sync(bf, Ct + ds * 8 * CT_LD + kc * 16, CT_LD);
                #pragma unroll
                for (int i = 0; i < a.num_elements; ++i)  a.x[i]  = wmma::__float_to_tf32(a.x[i]);
                #pragma unroll
                for (int i = 0; i < bf.num_elements; ++i) bf.x[i] = wmma::__float_to_tf32(bf.x[i]);
                wmma::mma_sync(p, a, bf, p);
            }
            wmma::store_matrix_sync(As + nc * 16 * AS_LD + kc * 16, p, AS_LD, wmma::mem_row_major);
        }
        __syncthreads();

        // ---- softmax over k (in place in As). 4 threads per n, 8 k each. ----
        {
            const int n = t >> 2, q = t & 3, ks = q * 8;
            const float x2n = x2p[n] + x2p[64 + n] + x2p[128 + n] + x2p[192 + n];
            float sl[8];
            float m = -1e30f;
            #pragma unroll
            for (int j = 0; j < 8; ++j) {
                int k = ks + j;
                float v = scs[k] * (x2n - 2.f * As[n * AS_LD + k] + c2s[k]);
                sl[j] = v; m = fmaxf(m, v);
            }
            m = fmaxf(m, __shfl_xor_sync(0xffffffffu, m, 1));
            m = fmaxf(m, __shfl_xor_sync(0xffffffffu, m, 2));
            float ssum = 0.f;
            #pragma unroll
            for (int j = 0; j < 8; ++j) { sl[j] = __expf(sl[j] - m); ssum += sl[j]; }
            ssum += __shfl_xor_sync(0xffffffffu, ssum, 1);
            ssum += __shfl_xor_sync(0xffffffffu, ssum, 2);
            const float inv = 1.0f / ssum;
            #pragma unroll
            for (int j = 0; j < 8; ++j) As[n * AS_LD + ks + j] = sl[j] * inv;
        }
        __syncthreads();

        // ---- per-CTA S_k += sum_n A[n][k] (warp 0, conflict-free columns) ----
        if (t < 32) {
            float acc = 0.f;
            #pragma unroll 8
            for (int n = 0; n < TN; ++n) acc += As[n * AS_LD + t];
            Ssm[t] += acc;
        }

        // ---- GEMM2: E[k][d] += sum_n A[n][k] * Xs[d][n]  (tf32 wmma) ----
        {
            #pragma unroll
            for (int ns = 0; ns < 8; ++ns) {
                wmma::fragment<wmma::matrix_a, 16, 16, 8, wmma::precision::tf32, wmma::col_major> a2[2];
                #pragma unroll
                for (int kc = 0; kc < 2; ++kc) {
                    wmma::load_matrix_sync(a2[kc], As + ns * 8 * AS_LD + kc * 16, AS_LD);
                    #pragma unroll
                    for (int i = 0; i < a2[kc].num_elements; ++i)
                        a2[kc].x[i] = wmma::__float_to_tf32(a2[kc].x[i]);
                }
                #pragma unroll
                for (int dt = 0; dt < 4; ++dt) {
                    wmma::fragment<wmma::matrix_b, 16, 16, 8, wmma::precision::tf32, wmma::col_major> b2;
                    wmma::load_matrix_sync(b2, Xs + (w * 64 + dt * 16) * XS_LD + ns * 8, XS_LD);
                    #pragma unroll
                    for (int i = 0; i < b2.num_elements; ++i)
                        b2.x[i] = wmma::__float_to_tf32(b2.x[i]);
                    wmma::mma_sync(eacc[0][dt], a2[0], b2, eacc[0][dt]);
                    wmma::mma_sync(eacc[1][dt], a2[1], b2, eacc[1][dt]);
                }
            }
        }
        __syncthreads();   // protect Xs/As before next subtile's staging
    }

    // ---- epilogue: dump accumulators, fold -S_k*c_k, atomicAdd to out ----
    float* Es = Xs;        // reuse (32 x ES_LD floats << XS_F)
    #pragma unroll
    for (int kc = 0; kc < 2; ++kc)
        #pragma unroll
        for (int dt = 0; dt < 4; ++dt)
            wmma::store_matrix_sync(Es + kc * 16 * ES_LD + w * 64 + dt * 16,
                                    eacc[kc][dt], ES_LD, wmma::mem_row_major);
    __syncthreads();

    for (int i = t; i < KK * DD; i += 256) {
        int k = i >> 9, d = i & 511;
        float v = Es[k * ES_LD + d] - Ssm[k] * Ct[d * CT_LD + k];
        atomicAdd(&out[((size_t)b * KK + k) * DD + d], v);
    }
}

extern "C" void kernel_launch(void* const* d_in, const int* in_sizes, int n_in,
                              void* d_out, int out_size) {
    (void)in_sizes; (void)n_in;
    const float* X     = (const float*)d_in[0];
    const float* CW    = (const float*)d_in[1];
    const float* scale = (const float*)d_in[2];
    float* out = (float*)d_out;

    cudaFuncSetAttribute(encoding_kernel,
                         cudaFuncAttributeMaxDynamicSharedMemorySize, SMEM_BYTES);

    // d_out is poisoned; atomics need zero init (graph-capturable memset node)
    cudaMemsetAsync(d_out, 0, (size_t)out_size * sizeof(float));

    dim3 grid(NN / CHUNK, BB);   // 32 x 8 = 256 CTAs
    dim3 block(256);
    encoding_kernel<<<grid, block, SMEM_BYTES>>>(X, CW, scale, out);
}

// round 2
// speedup vs baseline: 1.0723x; 1.0723x over previous
#include <cuda_runtime.h>
#include <cuda_bf16.h>
#include <mma.h>
#include <cstdint>

using namespace nvcuda;

// Problem constants
#define BB   8
#define DD   512
#define KK   32
#define NN   16384      // 128*128
#define TN   64         // n per subtile
#define CHUNK 1024      // n per CTA
#define NSUB (CHUNK/TN) // 16

// SMEM pitches (floats), all multiples of 4 (wmma ldm requirement)
#define XS_LD 68
#define CS_LD 516
#define AS_LD 36
#define ES_LD 516

// SMEM float counts
#define XS_F (DD*XS_LD)     // 34816
#define CS_F (KK*CS_LD)     // 16512
#define AS_F (TN*AS_LD)     // 2304 (x2 buffers)
#define X2_F (16*TN)        // 1024
#define SMEM_FLOATS (XS_F + CS_F + 2*AS_F + X2_F + 32 + 32 + 32)
#define SMEM_BYTES (SMEM_FLOATS * 4)   // 228224 B

__device__ __forceinline__ void cp_async16(void* smem_dst, const void* gmem_src) {
    uint32_t s = (uint32_t)__cvta_generic_to_shared(smem_dst);
    asm volatile("cp.async.cg.shared.global [%0], [%1], 16;\n" :: "r"(s), "l"(gmem_src));
}
__device__ __forceinline__ void cp_async_commit_wait() {
    asm volatile("cp.async.commit_group;\n" ::: "memory");
    asm volatile("cp.async.wait_group 0;\n" ::: "memory");
}

__global__ __launch_bounds__(512, 1)
void encoding_kernel(const float* __restrict__ X,
                     const float* __restrict__ CW,
                     const float* __restrict__ scale,
                     float* __restrict__ out)
{
    extern __shared__ float sm[];
    float* Xs  = sm;                 // [512][68]  X tile (raw -> tf32-rounded in place)
    float* Cs  = Xs + XS_F;          // [32][516]  codewords, pre-rounded to tf32
    float* As  = Cs + CS_F;          // [64][36]   GEMM1 partial (d-half 0), then A
    float* As2 = As + AS_F;          // [64][36]   GEMM1 partial (d-half 1)
    float* x2p = As2 + AS_F;         // [16][64]   x^2 partials
    float* Ssm = x2p + X2_F;         // [32]
    float* c2s = Ssm + 32;           // [32]
    float* scs = c2s + 32;           // [32]

    const int t = threadIdx.x;
    const int w = t >> 5;
    const int b = blockIdx.y;
    const int nbase = blockIdx.x * CHUNK;

    // ---- one-time: codewords (RN-rounded to tf32), scale, S=0, c2 ----
    for (int i = t; i < KK * DD; i += 512) {
        int k = i >> 9, d = i & 511;
        Cs[k * CS_LD + d] = wmma::__float_to_tf32(CW[i]);
    }
    if (t < 32) { Ssm[t] = 0.f; scs[t] = scale[t]; }
    __syncthreads();
    if (t < 32) {
        float s = 0.f;
        #pragma unroll 8
        for (int d = 0; d < DD; ++d) { float v = Cs[t * CS_LD + d]; s += v * v; }
        c2s[t] = s;   // consumed only after later barriers
    }

    // ---- persistent GEMM2 accumulators: warp w owns d in [w*32, w*32+32) ----
    wmma::fragment<wmma::accumulator, 16, 16, 8, float> eacc[2][2];
    #pragma unroll
    for (int kc = 0; kc < 2; ++kc)
        #pragma unroll
        for (int dt = 0; dt < 2; ++dt)
            wmma::fill_fragment(eacc[kc][dt], 0.f);

    const float* Xb = X + (size_t)b * DD * NN;

    for (int s = 0; s < NSUB; ++s) {
        const int n0 = nbase + s * TN;

        // ---- stage X[d, n0:n0+64] -> Xs via cp.async (16 x 16B per thread) ----
        {
            const int j  = t & 15;    // n-quad
            const int dr = t >> 4;    // 32 d-rows per pass
            const float* src = Xb + n0 + j * 4;
            #pragma unroll
            for (int r = 0; r < 16; ++r) {
                int d = r * 32 + dr;
                cp_async16(&Xs[d * XS_LD + j * 4], src + (size_t)d * NN);
            }
            cp_async_commit_wait();
        }
        __syncthreads();

        if (w < 8) {
            // ---- GEMM1 (warps 0-7): P[n][k] partials, d split in halves ----
            // warp = (nc in 0..3, half in 0..1); covers both k-chunks per warp.
            const int nc = w & 3, half = w >> 2;
            wmma::fragment<wmma::accumulator, 16, 16, 8, float> p0, p1;
            wmma::fill_fragment(p0, 0.f);
            wmma::fill_fragment(p1, 0.f);
            const int ds0 = half * 32;
            #pragma unroll 8
            for (int ds = ds0; ds < ds0 + 32; ++ds) {
                wmma::fragment<wmma::matrix_a, 16, 16, 8, wmma::precision::tf32, wmma::col_major> a;
                wmma::fragment<wmma::matrix_b, 16, 16, 8, wmma::precision::tf32, wmma::col_major> b0, b1;
                wmma::load_matrix_sync(a, Xs + ds * 8 * XS_LD + nc * 16, XS_LD);
                #pragma unroll
                for (int i = 0; i < a.num_elements; ++i) a.x[i] = wmma::__float_to_tf32(a.x[i]);
                wmma::load_matrix_sync(b0, Cs + ds * 8, CS_LD);
                wmma::load_matrix_sync(b1, Cs + 16 * CS_LD + ds * 8, CS_LD);
                wmma::mma_sync(p0, a, b0, p0);
                wmma::mma_sync(p1, a, b1, p1);
            }
            float* dst = half ? As2 : As;
            wmma::store_matrix_sync(dst + nc * 16 * AS_LD,      p0, AS_LD, wmma::mem_row_major);
            wmma::store_matrix_sync(dst + nc * 16 * AS_LD + 16, p1, AS_LD, wmma::mem_row_major);
        } else {
            // ---- x^2 + RN tf32 conversion pass (warps 8-15), vectorized ----
            const int tt = t - 256;
            const int j  = tt & 15;    // n-quad
            const int dp = tt >> 4;    // 16 d-partitions of 32 rows
            float a0 = 0.f, a1 = 0.f, a2 = 0.f, a3 = 0.f;
            #pragma unroll 8
            for (int r = 0; r < 32; ++r) {
                int d = dp * 32 + r;
                float4 v = *(float4*)&Xs[d * XS_LD + j * 4];
                a0 += v.x * v.x; a1 += v.y * v.y; a2 += v.z * v.z; a3 += v.w * v.w;
                v.x = wmma::__float_to_tf32(v.x);
                v.y = wmma::__float_to_tf32(v.y);
                v.z = wmma::__float_to_tf32(v.z);
                v.w = wmma::__float_to_tf32(v.w);
                *(float4*)&Xs[d * XS_LD + j * 4] = v;
            }
            x2p[dp * TN + j * 4 + 0] = a0;
            x2p[dp * TN + j * 4 + 1] = a1;
            x2p[dp * TN + j * 4 + 2] = a2;
            x2p[dp * TN + j * 4 + 3] = a3;
        }
        __syncthreads();

        // ---- softmax over k: 8 threads per pixel, 4 k each ----
        {
            const int n = t >> 3, q = t & 7, ks = q * 4;
            float x2n = x2p[(2 * q) * TN + n] + x2p[(2 * q + 1) * TN + n];
            x2n += __shfl_xor_sync(0xffffffffu, x2n, 1);
            x2n += __shfl_xor_sync(0xffffffffu, x2n, 2);
            x2n += __shfl_xor_sync(0xffffffffu, x2n, 4);
            float sl[4];
            float m = -1e30f;
            #pragma unroll
            for (int jj = 0; jj < 4; ++jj) {
                int k = ks + jj;
                float xc = As[n * AS_LD + k] + As2[n * AS_LD + k];
                float v = scs[k] * (x2n - 2.f * xc + c2s[k]);
                sl[jj] = v; m = fmaxf(m, v);
            }
            m = fmaxf(m, __shfl_xor_sync(0xffffffffu, m, 1));
            m = fmaxf(m, __shfl_xor_sync(0xffffffffu, m, 2));
            m = fmaxf(m, __shfl_xor_sync(0xffffffffu, m, 4));
            float ssum = 0.f;
            #pragma unroll
            for (int jj = 0; jj < 4; ++jj) { sl[jj] = __expf(sl[jj] - m); ssum += sl[jj]; }
            ssum += __shfl_xor_sync(0xffffffffu, ssum, 1);
            ssum += __shfl_xor_sync(0xffffffffu, ssum, 2);
            ssum += __shfl_xor_sync(0xffffffffu, ssum, 4);
            const float inv = 1.0f / ssum;
            #pragma unroll
            for (int jj = 0; jj < 4; ++jj)
                As[n * AS_LD + ks + jj] = wmma::__float_to_tf32(sl[jj] * inv);  // pre-round A
        }
        __syncthreads();

        // ---- per-CTA S_k += sum_n A[n][k] (warp 0) ----
        if (t < 32) {
            float acc = 0.f;
            #pragma unroll 8
            for (int n = 0; n < TN; ++n) acc += As[n * AS_LD + t];
            Ssm[t] += acc;
        }

        // ---- GEMM2 (all 16 warps): E[k][d] += sum_n A[n][k] * Xs[d][n] ----
        {
            #pragma unroll
            for (int ns = 0; ns < 8; ++ns) {
                wmma::fragment<wmma::matrix_a, 16, 16, 8, wmma::precision::tf32, wmma::col_major> a2[2];
                wmma::load_matrix_sync(a2[0], As + ns * 8 * AS_LD,      AS_LD);
                wmma::load_matrix_sync(a2[1], As + ns * 8 * AS_LD + 16, AS_LD);
                #pragma unroll
                for (int dt = 0; dt < 2; ++dt) {
                    wmma::fragment<wmma::matrix_b, 16, 16, 8, wmma::precision::tf32, wmma::col_major> b2;
                    wmma::load_matrix_sync(b2, Xs + (w * 32 + dt * 16) * XS_LD + ns * 8, XS_LD);
                    wmma::mma_sync(eacc[0][dt], a2[0], b2, eacc[0][dt]);
                    wmma::mma_sync(eacc[1][dt], a2[1], b2, eacc[1][dt]);
                }
            }
        }
        __syncthreads();   // protect Xs/As before next subtile's staging
    }

    // ---- epilogue: dump accumulators, fold -S_k*c_k, atomicAdd to out ----
    float* Es = Xs;        // reuse (32 x 516 floats << XS_F)
    #pragma unroll
    for (int kc = 0; kc < 2; ++kc)
        #pragma unroll
        for (int dt = 0; dt < 2; ++dt)
            wmma::store_matrix_sync(Es + kc * 16 * ES_LD + w * 32 + dt * 16,
                                    eacc[kc][dt], ES_LD, wmma::mem_row_major);
    __syncthreads();

    for (int i = t; i < KK * DD; i += 512) {
        int k = i >> 9, d = i & 511;
        float v = Es[k * ES_LD + d] - Ssm[k] * Cs[k * CS_LD + d];
        atomicAdd(&out[(size_t)b * KK * DD + i], v);
    }
}

extern "C" void kernel_launch(void* const* d_in, const int* in_sizes, int n_in,
                              void* d_out, int out_size) {
    (void)in_sizes; (void)n_in;
    const float* X     = (const float*)d_in[0];
    const float* CW    = (const float*)d_in[1];
    const float* scale = (const float*)d_in[2];
    float* out = (float*)d_out;

    cudaFuncSetAttribute(encoding_kernel,
                         cudaFuncAttributeMaxDynamicSharedMemorySize, SMEM_BYTES);

    // d_out is poisoned; atomics need zero init (graph-capturable memset node)
    cudaMemsetAsync(d_out, 0, (size_t)out_size * sizeof(float));

    dim3 grid(NN / CHUNK, BB);   // 16 x 8 = 128 CTAs
    dim3 block(512);
    encoding_kernel<<<grid, block, SMEM_BYTES>>>(X, CW, scale, out);
}